// round 5
// baseline (speedup 1.0000x reference)
#include <cuda_runtime.h>
#include <cuda_bf16.h>

#define CIN 128
#define CH  64
#define MAXN 100000
#define MAXG 512
#define MAXE 1600000

// Scratch (allocation-free rule: __device__ globals)
__device__ __align__(16) float g_dis[MAXN];
__device__ __align__(16) float g_h[(size_t)MAXN * CH];
__device__ __align__(16) float g_agg[(size_t)MAXN * CH];
__device__ int   g_deg[MAXN];
__device__ int   g_rowstart[MAXN + 1];
__device__ int   g_cursor[MAXN];
__device__ __align__(8) int2 g_emeta[MAXE];   // (src, norm-as-int)
__device__ float g_gsum[MAXG];
__device__ float g_gcnt[MAXG];

// ---------------------------------------------------------------------------
// K0: zero degree + graph accumulators
__global__ void k_init(int N, int G) {
    int i = blockIdx.x * blockDim.x + threadIdx.x;
    if (i < N) g_deg[i] = 0;
    if (i < G) { g_gsum[i] = 0.0f; g_gcnt[i] = 0.0f; }
}

// K1: integer in-degree at dst (self loop added later as +1)
__global__ void k_degree(const int* __restrict__ dst, int E) {
    int e = blockIdx.x * blockDim.x + threadIdx.x;
    if (e < E) atomicAdd(&g_deg[dst[e]], 1);
}

// K2: dis = rsqrt(deg + 1)
__global__ void k_rsqrt(int N) {
    int i = blockIdx.x * blockDim.x + threadIdx.x;
    if (i < N) g_dis[i] = rsqrtf((float)(g_deg[i] + 1));
}

// K3: single-block exclusive scan of g_deg -> g_rowstart / g_cursor
__global__ __launch_bounds__(1024) void k_scan(int N, int E) {
    __shared__ int sums[1024];
    int t = threadIdx.x;
    int chunk = (N + 1023) / 1024;
    int start = t * chunk;
    int end = start + chunk; if (end > N) end = N;
    int s = 0;
    for (int i = start; i < end; i++) s += g_deg[i];
    sums[t] = s;
    __syncthreads();
    for (int off = 1; off < 1024; off <<= 1) {
        int v = (t >= off) ? sums[t - off] : 0;
        __syncthreads();
        if (t >= off) sums[t] += v;
        __syncthreads();
    }
    int run = (t == 0) ? 0 : sums[t - 1];
    for (int i = start; i < end; i++) {
        g_rowstart[i] = run; g_cursor[i] = run;
        run += g_deg[i];
    }
    if (t == 0) g_rowstart[N] = E;
}

// K4: fill CSR entries (src, precomputed sym norm)
__global__ void k_fill(const int* __restrict__ src, const int* __restrict__ dst, int E) {
    int e = blockIdx.x * blockDim.x + threadIdx.x;
    if (e >= E) return;
    int s = src[e], d = dst[e];
    int slot = atomicAdd(&g_cursor[d], 1);
    int2 m; m.x = s; m.y = __float_as_int(g_dis[s] * g_dis[d]);
    g_emeta[slot] = m;
}

// ---------------------------------------------------------------------------
// GEMM: 64-row x 64-col tile, thread = 4x4 register block, K chunked by 64
// through STATIC 32 KB smem (no cudaFuncSetAttribute needed).
// FIRST: input = x.  !FIRST: input = relu(g_agg + bias).
// Epilogue: g_h = result; g_agg = result * dis^2 (self-loop term).
template<int KD, bool FIRST>
__global__ __launch_bounds__(256) void k_gemm(
    const float* __restrict__ xin, const float* __restrict__ W,
    const float* __restrict__ bias, int N)
{
    __shared__ float Ws[64][64];   // W[k0+kk][c], 16 KB
    __shared__ float xs[64][64];   // in[row][k0+kk], 16 KB
    int tid = threadIdx.x;
    int rowBase = blockIdx.x * 64;
    int tx = tid & 15, ty = tid >> 4;
    int r0 = ty * 4, c0 = tx * 4;

    float4 acc[4];
#pragma unroll
    for (int r = 0; r < 4; r++) acc[r] = make_float4(0.f, 0.f, 0.f, 0.f);

    for (int k0 = 0; k0 < KD; k0 += 64) {
        // stage W chunk: rows k0..k0+63, 64 cols
        {
            const float4* W4 = (const float4*)(W + (size_t)k0 * 64);
            for (int i = tid; i < 64 * 16; i += 256)
                ((float4*)&Ws[0][0])[i] = W4[i];
        }
        // stage input chunk: 64 rows x cols k0..k0+63
        for (int i = tid; i < 64 * 16; i += 256) {
            int r = i >> 4, c = i & 15;
            int row = rowBase + r;
            float4 v = make_float4(0.f, 0.f, 0.f, 0.f);
            if (row < N) {
                if (FIRST) {
                    v = ((const float4*)xin)[(size_t)row * (KD / 4) + (k0 / 4) + c];
                } else {
                    float4 a = ((const float4*)g_agg)[(size_t)row * (KD / 4) + (k0 / 4) + c];
                    float4 b = ((const float4*)bias)[(k0 / 4) + c];
                    v.x = fmaxf(a.x + b.x, 0.f); v.y = fmaxf(a.y + b.y, 0.f);
                    v.z = fmaxf(a.z + b.z, 0.f); v.w = fmaxf(a.w + b.w, 0.f);
                }
            }
            ((float4*)&xs[r][0])[c] = v;
        }
        __syncthreads();

#pragma unroll 4
        for (int kk = 0; kk < 64; kk += 4) {
            float4 xr[4], wr[4];
#pragma unroll
            for (int r = 0; r < 4; r++) xr[r] = *(const float4*)&xs[r0 + r][kk];
#pragma unroll
            for (int j = 0; j < 4; j++) wr[j] = *(const float4*)&Ws[kk + j][c0];
#pragma unroll
            for (int r = 0; r < 4; r++) {
                float xv0 = xr[r].x, xv1 = xr[r].y, xv2 = xr[r].z, xv3 = xr[r].w;
                acc[r].x += xv0 * wr[0].x; acc[r].y += xv0 * wr[0].y;
                acc[r].z += xv0 * wr[0].z; acc[r].w += xv0 * wr[0].w;
                acc[r].x += xv1 * wr[1].x; acc[r].y += xv1 * wr[1].y;
                acc[r].z += xv1 * wr[1].z; acc[r].w += xv1 * wr[1].w;
                acc[r].x += xv2 * wr[2].x; acc[r].y += xv2 * wr[2].y;
                acc[r].z += xv2 * wr[2].z; acc[r].w += xv2 * wr[2].w;
                acc[r].x += xv3 * wr[3].x; acc[r].y += xv3 * wr[3].y;
                acc[r].z += xv3 * wr[3].z; acc[r].w += xv3 * wr[3].w;
            }
        }
        __syncthreads();
    }

#pragma unroll
    for (int r = 0; r < 4; r++) {
        int row = rowBase + r0 + r;
        if (row < N) {
            float d = g_dis[row], d2 = d * d;
            ((float4*)(g_h + (size_t)row * CH))[tx] = acc[r];
            float4 ag = make_float4(acc[r].x * d2, acc[r].y * d2,
                                    acc[r].z * d2, acc[r].w * d2);
            ((float4*)(g_agg + (size_t)row * CH))[tx] = ag;
        }
    }
}

// ---------------------------------------------------------------------------
// Pull aggregation: 1 warp per node. 16 lanes x 2 edges per iteration.
// g_agg[n] (holds self term) += sum over in-edges of h[src]*norm. No atomics.
__global__ __launch_bounds__(256) void k_gather(int N) {
    int warp = (blockIdx.x * 256 + threadIdx.x) >> 5;
    if (warp >= N) return;
    int lane = threadIdx.x & 31;
    int grp = lane >> 4, c = lane & 15;
    int rs = g_rowstart[warp], re = g_rowstart[warp + 1];
    float4 acc = make_float4(0.f, 0.f, 0.f, 0.f);
    for (int i = rs + grp; i < re; i += 2) {
        int2 m = g_emeta[i];
        float nm = __int_as_float(m.y);
        float4 v = ((const float4*)g_h)[(size_t)m.x * (CH / 4) + c];
        acc.x += v.x * nm; acc.y += v.y * nm;
        acc.z += v.z * nm; acc.w += v.w * nm;
    }
    acc.x += __shfl_xor_sync(0xffffffffu, acc.x, 16);
    acc.y += __shfl_xor_sync(0xffffffffu, acc.y, 16);
    acc.z += __shfl_xor_sync(0xffffffffu, acc.z, 16);
    acc.w += __shfl_xor_sync(0xffffffffu, acc.w, 16);
    if (grp == 0) {
        float4* p = (float4*)g_agg + (size_t)warp * (CH / 4) + c;
        float4 s = *p;
        s.x += acc.x; s.y += acc.y; s.z += acc.z; s.w += acc.w;
        *p = s;
    }
}

// ---------------------------------------------------------------------------
// Pool: per-node s = relu(agg2 + b2) . Wl  -> segment sum per graph
__global__ __launch_bounds__(256) void k_pool(
    const int* __restrict__ batch, const float* __restrict__ b2,
    const float* __restrict__ Wl, int N)
{
    int tid = blockIdx.x * blockDim.x + threadIdx.x;
    int n = tid >> 4, l = tid & 15;
    if (n >= N) return;
    float4 v = ((const float4*)g_agg)[(size_t)n * (CH / 4) + l];
    float4 b = ((const float4*)b2)[l];
    float4 w = ((const float4*)Wl)[l];
    float s = fmaxf(v.x + b.x, 0.f) * w.x + fmaxf(v.y + b.y, 0.f) * w.y
            + fmaxf(v.z + b.z, 0.f) * w.z + fmaxf(v.w + b.w, 0.f) * w.w;
    s += __shfl_down_sync(0xffffffffu, s, 8, 16);
    s += __shfl_down_sync(0xffffffffu, s, 4, 16);
    s += __shfl_down_sync(0xffffffffu, s, 2, 16);
    s += __shfl_down_sync(0xffffffffu, s, 1, 16);
    if (l == 0) {
        int g = batch[n];
        atomicAdd(&g_gsum[g], s);
        atomicAdd(&g_gcnt[g], 1.0f);
    }
}

__global__ void k_logits(float* __restrict__ out, const float* __restrict__ bl, int G) {
    int g = blockIdx.x * blockDim.x + threadIdx.x;
    if (g < G) out[g] = g_gsum[g] / fmaxf(g_gcnt[g], 1.0f) + bl[0];
}

// ---------------------------------------------------------------------------
extern "C" void kernel_launch(void* const* d_in, const int* in_sizes, int n_in,
                              void* d_out, int out_size)
{
    const float* x     = (const float*)d_in[0];
    const int*   ei    = (const int*)  d_in[1];
    const int*   batch = (const int*)  d_in[2];
    const float* W1    = (const float*)d_in[3];
    const float* b1    = (const float*)d_in[4];
    const float* W2    = (const float*)d_in[5];
    const float* b2    = (const float*)d_in[6];
    const float* Wl    = (const float*)d_in[7];
    const float* bl    = (const float*)d_in[8];

    int N = in_sizes[0] / CIN;
    int E = in_sizes[1] / 2;
    int G = out_size;
    const int* src = ei;
    const int* dst = ei + E;
    float* out = (float*)d_out;

    int nb = (N + 255) / 256;
    int eb = (E + 255) / 256;
    int gb = (N + 63) / 64;
    int ab = (N + 7) / 8;           // gather: warp per node
    int pb = (N * 16 + 255) / 256;

    k_init   <<<nb, 256>>>(N, G);
    k_degree <<<eb, 256>>>(dst, E);
    k_rsqrt  <<<nb, 256>>>(N);
    k_scan   <<<1, 1024>>>(N, E);
    k_fill   <<<eb, 256>>>(src, dst, E);
    k_gemm<CIN, true>  <<<gb, 256>>>(x, W1, nullptr, N);
    k_gather <<<ab, 256>>>(N);
    k_gemm<CH, false>  <<<gb, 256>>>(nullptr, W2, b1, N);
    k_gather <<<ab, 256>>>(N);
    k_pool   <<<pb, 256>>>(batch, b2, Wl, N);
    k_logits <<<(G + 255) / 256, 256>>>(out, bl, G);
}

// round 7
// speedup vs baseline: 1.6721x; 1.6721x over previous
#include <cuda_runtime.h>
#include <cuda_bf16.h>

#define CIN 128
#define CH  64
#define MAXN 100000
#define MAXG 512
#define MAXE 1600000
#define SCAN_TILE 1024
#define MAXB ((MAXN + SCAN_TILE - 1) / SCAN_TILE)

// Scratch (allocation-free rule: __device__ globals)
__device__ __align__(16) float g_dis[MAXN];
__device__ __align__(16) float g_h[(size_t)MAXN * CH];
__device__ __align__(16) float g_agg[(size_t)MAXN * CH];
__device__ int   g_deg[MAXN];
__device__ int   g_rowstart[MAXN + 1];
__device__ int   g_cursor[MAXN];
__device__ int   g_bsum[MAXB];
__device__ __align__(8) int2 g_emeta[MAXE];   // (src, norm-as-int)
__device__ float g_gsum[MAXG];
__device__ float g_gcnt[MAXG];

// ---------------------------------------------------------------------------
// K0: zero degree + graph accumulators
__global__ void k_init(int N, int G) {
    int i = blockIdx.x * blockDim.x + threadIdx.x;
    if (i < N) g_deg[i] = 0;
    if (i < G) { g_gsum[i] = 0.0f; g_gcnt[i] = 0.0f; }
}

// K1: integer in-degree at dst (self loop added later as +1)
__global__ void k_degree(const int* __restrict__ dst, int E) {
    int e = blockIdx.x * blockDim.x + threadIdx.x;
    if (e < E) atomicAdd(&g_deg[dst[e]], 1);
}

// K2: dis = rsqrt(deg + 1)
__global__ void k_rsqrt(int N) {
    int i = blockIdx.x * blockDim.x + threadIdx.x;
    if (i < N) g_dis[i] = rsqrtf((float)(g_deg[i] + 1));
}

// ---------------------------------------------------------------------------
// Multi-block exclusive scan of g_deg (3 kernels, SCAN_TILE elems per block)
// A: per-block tile sum
__global__ __launch_bounds__(256) void k_scanA(int N) {
    __shared__ int sh[256];
    int t = threadIdx.x;
    int base = blockIdx.x * SCAN_TILE + t * 4;
    int s = 0;
#pragma unroll
    for (int j = 0; j < 4; j++) {
        int i = base + j;
        if (i < N) s += g_deg[i];
    }
    sh[t] = s;
    __syncthreads();
    for (int off = 128; off > 0; off >>= 1) {
        if (t < off) sh[t] += sh[t + off];
        __syncthreads();
    }
    if (t == 0) g_bsum[blockIdx.x] = sh[0];
}

// B: single-block exclusive scan of block sums (NB <= 128)
__global__ __launch_bounds__(128) void k_scanB(int NB) {
    __shared__ int sh[128];
    int t = threadIdx.x;
    sh[t] = (t < NB) ? g_bsum[t] : 0;
    __syncthreads();
    for (int off = 1; off < 128; off <<= 1) {
        int v = (t >= off) ? sh[t - off] : 0;
        __syncthreads();
        sh[t] += v;
        __syncthreads();
    }
    if (t < NB) g_bsum[t] = (t == 0) ? 0 : sh[t - 1];
}

// C: per-tile exclusive scan + block offset -> rowstart / cursor
__global__ __launch_bounds__(256) void k_scanC(int N, int E) {
    __shared__ int sh[256];
    int t = threadIdx.x;
    int base = blockIdx.x * SCAN_TILE + t * 4;
    int d[4];
    int s = 0;
#pragma unroll
    for (int j = 0; j < 4; j++) {
        int i = base + j;
        d[j] = (i < N) ? g_deg[i] : 0;
        s += d[j];
    }
    sh[t] = s;
    __syncthreads();
    for (int off = 1; off < 256; off <<= 1) {
        int v = (t >= off) ? sh[t - off] : 0;
        __syncthreads();
        sh[t] += v;
        __syncthreads();
    }
    int run = g_bsum[blockIdx.x] + ((t == 0) ? 0 : sh[t - 1]);
#pragma unroll
    for (int j = 0; j < 4; j++) {
        int i = base + j;
        if (i < N) { g_rowstart[i] = run; g_cursor[i] = run; }
        run += d[j];
    }
    if (blockIdx.x == 0 && t == 0) g_rowstart[N] = E;
}

// K4: fill CSR entries (src, precomputed sym norm)
__global__ void k_fill(const int* __restrict__ src, const int* __restrict__ dst, int E) {
    int e = blockIdx.x * blockDim.x + threadIdx.x;
    if (e >= E) return;
    int s = src[e], d = dst[e];
    int slot = atomicAdd(&g_cursor[d], 1);
    int2 m; m.x = s; m.y = __float_as_int(g_dis[s] * g_dis[d]);
    g_emeta[slot] = m;
}

// ---------------------------------------------------------------------------
// GEMM: 64-row x 64-col tile, thread = 4x4 register block, K chunked by 64
// through STATIC 32 KB smem.
// FIRST: input = x.  !FIRST: input = relu(g_agg + bias).
// Epilogue: g_h = result; g_agg = result * dis^2 (self-loop term).
template<int KD, bool FIRST>
__global__ __launch_bounds__(256) void k_gemm(
    const float* __restrict__ xin, const float* __restrict__ W,
    const float* __restrict__ bias, int N)
{
    __shared__ float Ws[64][64];   // W[k0+kk][c], 16 KB
    __shared__ float xs[64][64];   // in[row][k0+kk], 16 KB
    int tid = threadIdx.x;
    int rowBase = blockIdx.x * 64;
    int tx = tid & 15, ty = tid >> 4;
    int r0 = ty * 4, c0 = tx * 4;

    float4 acc[4];
#pragma unroll
    for (int r = 0; r < 4; r++) acc[r] = make_float4(0.f, 0.f, 0.f, 0.f);

    for (int k0 = 0; k0 < KD; k0 += 64) {
        {
            const float4* W4 = (const float4*)(W + (size_t)k0 * 64);
            for (int i = tid; i < 64 * 16; i += 256)
                ((float4*)&Ws[0][0])[i] = W4[i];
        }
        for (int i = tid; i < 64 * 16; i += 256) {
            int r = i >> 4, c = i & 15;
            int row = rowBase + r;
            float4 v = make_float4(0.f, 0.f, 0.f, 0.f);
            if (row < N) {
                if (FIRST) {
                    v = ((const float4*)xin)[(size_t)row * (KD / 4) + (k0 / 4) + c];
                } else {
                    float4 a = ((const float4*)g_agg)[(size_t)row * (KD / 4) + (k0 / 4) + c];
                    float4 b = ((const float4*)bias)[(k0 / 4) + c];
                    v.x = fmaxf(a.x + b.x, 0.f); v.y = fmaxf(a.y + b.y, 0.f);
                    v.z = fmaxf(a.z + b.z, 0.f); v.w = fmaxf(a.w + b.w, 0.f);
                }
            }
            ((float4*)&xs[r][0])[c] = v;
        }
        __syncthreads();

#pragma unroll 4
        for (int kk = 0; kk < 64; kk += 4) {
            float4 xr[4], wr[4];
#pragma unroll
            for (int r = 0; r < 4; r++) xr[r] = *(const float4*)&xs[r0 + r][kk];
#pragma unroll
            for (int j = 0; j < 4; j++) wr[j] = *(const float4*)&Ws[kk + j][c0];
#pragma unroll
            for (int r = 0; r < 4; r++) {
                float xv0 = xr[r].x, xv1 = xr[r].y, xv2 = xr[r].z, xv3 = xr[r].w;
                acc[r].x += xv0 * wr[0].x; acc[r].y += xv0 * wr[0].y;
                acc[r].z += xv0 * wr[0].z; acc[r].w += xv0 * wr[0].w;
                acc[r].x += xv1 * wr[1].x; acc[r].y += xv1 * wr[1].y;
                acc[r].z += xv1 * wr[1].z; acc[r].w += xv1 * wr[1].w;
                acc[r].x += xv2 * wr[2].x; acc[r].y += xv2 * wr[2].y;
                acc[r].z += xv2 * wr[2].z; acc[r].w += xv2 * wr[2].w;
                acc[r].x += xv3 * wr[3].x; acc[r].y += xv3 * wr[3].y;
                acc[r].z += xv3 * wr[3].z; acc[r].w += xv3 * wr[3].w;
            }
        }
        __syncthreads();
    }

#pragma unroll
    for (int r = 0; r < 4; r++) {
        int row = rowBase + r0 + r;
        if (row < N) {
            float d = g_dis[row], d2 = d * d;
            ((float4*)(g_h + (size_t)row * CH))[tx] = acc[r];
            float4 ag = make_float4(acc[r].x * d2, acc[r].y * d2,
                                    acc[r].z * d2, acc[r].w * d2);
            ((float4*)(g_agg + (size_t)row * CH))[tx] = ag;
        }
    }
}

// ---------------------------------------------------------------------------
// Pull aggregation: 1 warp per node. 16 lanes x 2 edges per iteration.
// g_agg[n] (holds self term) += sum over in-edges of h[src]*norm. No atomics.
__global__ __launch_bounds__(256) void k_gather(int N) {
    int warp = (blockIdx.x * 256 + threadIdx.x) >> 5;
    if (warp >= N) return;
    int lane = threadIdx.x & 31;
    int grp = lane >> 4, c = lane & 15;
    int rs = g_rowstart[warp], re = g_rowstart[warp + 1];
    float4 acc = make_float4(0.f, 0.f, 0.f, 0.f);
    for (int i = rs + grp; i < re; i += 2) {
        int2 m = g_emeta[i];
        float nm = __int_as_float(m.y);
        float4 v = ((const float4*)g_h)[(size_t)m.x * (CH / 4) + c];
        acc.x += v.x * nm; acc.y += v.y * nm;
        acc.z += v.z * nm; acc.w += v.w * nm;
    }
    acc.x += __shfl_xor_sync(0xffffffffu, acc.x, 16);
    acc.y += __shfl_xor_sync(0xffffffffu, acc.y, 16);
    acc.z += __shfl_xor_sync(0xffffffffu, acc.z, 16);
    acc.w += __shfl_xor_sync(0xffffffffu, acc.w, 16);
    if (grp == 0) {
        float4* p = (float4*)g_agg + (size_t)warp * (CH / 4) + c;
        float4 s = *p;
        s.x += acc.x; s.y += acc.y; s.z += acc.z; s.w += acc.w;
        *p = s;
    }
}

// ---------------------------------------------------------------------------
// Pool: per-node s = relu(agg2 + b2) . Wl  -> segment sum per graph
__global__ __launch_bounds__(256) void k_pool(
    const int* __restrict__ batch, const float* __restrict__ b2,
    const float* __restrict__ Wl, int N)
{
    int tid = blockIdx.x * blockDim.x + threadIdx.x;
    int n = tid >> 4, l = tid & 15;
    if (n >= N) return;
    float4 v = ((const float4*)g_agg)[(size_t)n * (CH / 4) + l];
    float4 b = ((const float4*)b2)[l];
    float4 w = ((const float4*)Wl)[l];
    float s = fmaxf(v.x + b.x, 0.f) * w.x + fmaxf(v.y + b.y, 0.f) * w.y
            + fmaxf(v.z + b.z, 0.f) * w.z + fmaxf(v.w + b.w, 0.f) * w.w;
    s += __shfl_down_sync(0xffffffffu, s, 8, 16);
    s += __shfl_down_sync(0xffffffffu, s, 4, 16);
    s += __shfl_down_sync(0xffffffffu, s, 2, 16);
    s += __shfl_down_sync(0xffffffffu, s, 1, 16);
    if (l == 0) {
        int g = batch[n];
        atomicAdd(&g_gsum[g], s);
        atomicAdd(&g_gcnt[g], 1.0f);
    }
}

__global__ void k_logits(float* __restrict__ out, const float* __restrict__ bl, int G) {
    int g = blockIdx.x * blockDim.x + threadIdx.x;
    if (g < G) out[g] = g_gsum[g] / fmaxf(g_gcnt[g], 1.0f) + bl[0];
}

// ---------------------------------------------------------------------------
extern "C" void kernel_launch(void* const* d_in, const int* in_sizes, int n_in,
                              void* d_out, int out_size)
{
    const float* x     = (const float*)d_in[0];
    const int*   ei    = (const int*)  d_in[1];
    const int*   batch = (const int*)  d_in[2];
    const float* W1    = (const float*)d_in[3];
    const float* b1    = (const float*)d_in[4];
    const float* W2    = (const float*)d_in[5];
    const float* b2    = (const float*)d_in[6];
    const float* Wl    = (const float*)d_in[7];
    const float* bl    = (const float*)d_in[8];

    int N = in_sizes[0] / CIN;
    int E = in_sizes[1] / 2;
    int G = out_size;
    const int* src = ei;
    const int* dst = ei + E;
    float* out = (float*)d_out;

    int nb = (N + 255) / 256;
    int eb = (E + 255) / 256;
    int gb = (N + 63) / 64;
    int ab = (N + 7) / 8;                       // gather: warp per node
    int pb = (N * 16 + 255) / 256;
    int NB = (N + SCAN_TILE - 1) / SCAN_TILE;   // scan blocks (98)

    k_init   <<<nb, 256>>>(N, G);
    k_degree <<<eb, 256>>>(dst, E);
    k_rsqrt  <<<nb, 256>>>(N);
    k_scanA  <<<NB, 256>>>(N);
    k_scanB  <<<1, 128>>>(NB);
    k_scanC  <<<NB, 256>>>(N, E);
    k_fill   <<<eb, 256>>>(src, dst, E);
    k_gemm<CIN, true>  <<<gb, 256>>>(x, W1, nullptr, N);
    k_gather <<<ab, 256>>>(N);
    k_gemm<CH, false>  <<<gb, 256>>>(nullptr, W2, b1, N);
    k_gather <<<ab, 256>>>(N);
    k_pool   <<<pb, 256>>>(batch, b2, Wl, N);
    k_logits <<<(G + 255) / 256, 256>>>(out, bl, G);
}